// round 4
// baseline (speedup 1.0000x reference)
#include <cuda_runtime.h>
#include <math.h>

#define N_LOC 4096
#define N_REP 128
#define M_NBR 48

#define APK_FLOATS 8448          // packed lower triangle, rows padded to 4
#define XS_STRIDE 128

// smem layout (floats)
#define OFF_APK  0
#define OFF_XS   (APK_FLOATS)
#define OFF_DIAG (OFF_XS + M_NBR * XS_STRIDE)
#define OFF_INVD (OFF_DIAG + 128)
#define OFF_INVL (OFF_INVD + 32)
#define OFF_SCAL (OFF_INVL + 32 * 33)
#define SMEM_FLOATS (OFF_SCAL + 48)

// packed row offset: row i (padded to 4) start
__device__ __forceinline__ int aoff(int i) {
    int q = i >> 2;
    return 4 * (q + 1) * (2 * q + (i & 3));
}

__device__ __forceinline__ void tridec(int t, int& row, int& col) {
    int r = (int)((sqrtf(8.0f * (float)t + 1.0f) - 1.0f) * 0.5f);
    while ((r + 1) * (r + 2) / 2 <= t) ++r;
    while (r * (r + 1) / 2 > t) --r;
    row = r;
    col = t - r * (r + 1) / 2;
}

__global__ __launch_bounds__(512, 2)
void otm_fused_kernel(const float* __restrict__ aug,
                      const float* __restrict__ theta,
                      const float* __restrict__ scales,
                      const float* __restrict__ nug_mean,
                      const int* __restrict__ batch_idx,
                      float* __restrict__ out)
{
    const int N = blockIdx.x;
    const int tid = threadIdx.x;

    float* g_out = out + (size_t)N * 16384;
    float* c_out = out + (size_t)N_LOC * 16384 + (size_t)N * 16384;

    if (batch_idx[N] == 0) {
        for (int idx = tid; idx < 16384; idx += 512) {
            float v = ((idx >> 7) == (idx & 127)) ? 1.0f : 0.0f;
            g_out[idx] = v;
            c_out[idx] = v;
        }
        return;
    }

    extern __shared__ float smem[];
    float* Apk   = smem + OFF_APK;    // packed lower triangle
    float* xs    = smem + OFF_XS;     // [48][128] k-major
    float* diag  = smem + OFF_DIAG;   // [128]
    float* invd  = smem + OFF_INVD;   // [32]
    float* invL  = smem + OFF_INVL;   // [32][33]
    float* scalm = smem + OFF_SCAL;   // [48]

    const float t2 = theta[2];
    const float t3 = theta[3];
    const float t4 = theta[4];
    const float t5 = theta[5];
    const float ls = expf(t5) * 1.7320508075688772f;
    const float inv_ls2 = 1.0f / (ls * ls);
    const float sig2 = expf(2.0f * (logf(scales[N]) * t4 + t3));
    const float inv_nug = 1.0f / nug_mean[N];

    if (tid < M_NBR) {
        scalm[tid] = expf(-0.5f * (float)(tid + 1) * expf(t2));
    }
    __syncthreads();

    // ---- load xs[m][i] = clean(aug[i,N,1+m]) * scalm[m] ----
    {
        const float* base = aug + (size_t)N * (M_NBR + 1) + 1;
        for (int idx = tid; idx < N_REP * M_NBR; idx += 512) {
            int i = idx / M_NBR;
            int m = idx - i * M_NBR;
            float v = base[(size_t)i * ((size_t)N_LOC * (M_NBR + 1)) + m];
            if (v != v) v = 0.0f;
            xs[m * XS_STRIDE + i] = v * scalm[m];
        }
    }
    __syncthreads();

    // ---- diag[i] = sum_m xs[m][i]^2 ----
    if (tid < N_REP) {
        float d = 0.0f;
        #pragma unroll
        for (int m = 0; m < M_NBR; ++m) {
            float v = xs[m * XS_STRIDE + tid];
            d = fmaf(v, v, d);
        }
        diag[tid] = d;
    }
    __syncthreads();

    // ---- Gram + epilogue, LOWER TRIANGLE only: 528 4x4 tiles ----
    for (int t = tid; t < 528; t += 512) {
        int ti, tj;
        tridec(t, ti, tj);
        const int ib = ti * 4, jb = tj * 4;

        float acc[16];
        #pragma unroll
        for (int k = 0; k < 16; ++k) acc[k] = 0.0f;

        #pragma unroll
        for (int m = 0; m < M_NBR; ++m) {
            const float* row = xs + m * XS_STRIDE;
            float4 a = *reinterpret_cast<const float4*>(row + ib);
            float4 b = *reinterpret_cast<const float4*>(row + jb);
            float av[4] = {a.x, a.y, a.z, a.w};
            float bv[4] = {b.x, b.y, b.z, b.w};
            #pragma unroll
            for (int r = 0; r < 4; ++r)
                #pragma unroll
                for (int c = 0; c < 4; ++c)
                    acc[r * 4 + c] = fmaf(av[r], bv[c], acc[r * 4 + c]);
        }

        float di[4], dj[4];
        #pragma unroll
        for (int r = 0; r < 4; ++r) di[r] = diag[ib + r];
        #pragma unroll
        for (int c = 0; c < 4; ++c) dj[c] = diag[jb + c];

        #pragma unroll
        for (int r = 0; r < 4; ++r) {
            const int i = ib + r;
            const int ro = aoff(i);
            #pragma unroll
            for (int c = 0; c < 4; ++c) {
                const int j = jb + c;
                if (j <= i) {
                    float G = acc[r * 4 + c];
                    float sq = fmaxf((di[r] + dj[c] - 2.0f * G) * inv_ls2, 0.0f);
                    // s3 = sqrt(3*sq) via fast rsqrt (exact 0 at sq=0)
                    float s3 = 1.7320508075688772f * sq * __frsqrt_rn(fmaxf(sq, 1e-30f));
                    float mat = (1.0f + s3) * __expf(-s3);
                    float val = (G + sig2 * mat) * inv_nug + ((i == j) ? 1.0f : 0.0f);
                    Apk[ro + j] = val;
                }
            }
        }
    }
    __syncthreads();

    // ---- write g (full, mirrored from packed lower) ----
    {
        const int i0 = (tid >> 4) * 4;
        const int j0 = (tid & 15) * 4;
        int aj0[8];
        #pragma unroll
        for (int c = 0; c < 8; ++c) {
            int j = (c < 4) ? (j0 + c) : (64 + j0 + (c - 4));
            aj0[c] = aoff(j);
        }
        #pragma unroll
        for (int r = 0; r < 4; ++r) {
            const int i = i0 + r;
            const int ro = aoff(i);
            float va[8];
            #pragma unroll
            for (int c = 0; c < 8; ++c) {
                int j = (c < 4) ? (j0 + c) : (64 + j0 + (c - 4));
                va[c] = (j <= i) ? Apk[ro + j] : Apk[aj0[c] + i];
            }
            *reinterpret_cast<float4*>(g_out + i * 128 + j0) =
                make_float4(va[0], va[1], va[2], va[3]);
            *reinterpret_cast<float4*>(g_out + i * 128 + 64 + j0) =
                make_float4(va[4], va[5], va[6], va[7]);
        }
    }

    // ================= Blocked Cholesky (lower), NB=32, packed A ==========
    #pragma unroll 1
    for (int kb = 0; kb < 4; ++kb) {
        const int k0 = kb * 32;
        __syncthreads();

        // --- (a) warp0: factor 32x32 diag block; lane owns row ---
        if (tid < 32) {
            const int lane = tid;
            const int ro = aoff(k0 + lane) + k0;
            float rw[32];
            #pragma unroll
            for (int j = 0; j < 32; ++j)
                rw[j] = (j <= lane) ? Apk[ro + j] : 0.0f;

            #pragma unroll
            for (int c = 0; c < 32; ++c) {
                float dcc = __shfl_sync(0xffffffffu, rw[c], c);
                float lcc = sqrtf(dcc);
                float inv = 1.0f / lcc;
                if (lane == c) { rw[c] = lcc; invd[c] = inv; }
                else if (lane > c) rw[c] *= inv;
                float vc = rw[c];
                #pragma unroll
                for (int j = c + 1; j < 32; ++j) {
                    float vj = __shfl_sync(0xffffffffu, vc, j);
                    if (lane >= j) rw[j] -= vc * vj;
                }
            }
            #pragma unroll
            for (int j = 0; j < 32; ++j)
                if (j <= lane) Apk[ro + j] = rw[j];
            __syncwarp();

            // --- (a2) lane computes column `lane` of inv(L11) ---
            {
                float x[32];
                #pragma unroll
                for (int r = 0; r < 32; ++r) {
                    float s = (r == lane) ? 1.0f : 0.0f;
                    const int rr = aoff(k0 + r) + k0;
                    #pragma unroll
                    for (int d = 0; d < 32; ++d)
                        if (d < r) s -= Apk[rr + d] * x[d];
                    x[r] = s * invd[r];
                    invL[r * 33 + lane] = x[r];
                }
            }
        }
        __syncthreads();

        const int rem = 96 - k0;
        if (rem > 0) {
            // --- (b) panel solve: row i = invL * row (depth 32, no chain) ---
            if (tid < rem) {
                const int i = k0 + 32 + tid;
                const int ro = aoff(i) + k0;
                float r[32];
                #pragma unroll
                for (int c4 = 0; c4 < 8; ++c4) {
                    float4 v = *reinterpret_cast<const float4*>(&Apk[ro + c4 * 4]);
                    r[c4 * 4 + 0] = v.x; r[c4 * 4 + 1] = v.y;
                    r[c4 * 4 + 2] = v.z; r[c4 * 4 + 3] = v.w;
                }
                #pragma unroll
                for (int c4 = 0; c4 < 8; ++c4) {
                    float o[4];
                    #pragma unroll
                    for (int cc = 0; cc < 4; ++cc) {
                        const int c = c4 * 4 + cc;
                        float s = 0.0f;
                        #pragma unroll
                        for (int d = 0; d < 32; ++d)
                            if (d <= c) s = fmaf(invL[c * 33 + d], r[d], s);
                        o[cc] = s;
                    }
                    *reinterpret_cast<float4*>(&Apk[ro + c4 * 4]) =
                        make_float4(o[0], o[1], o[2], o[3]);
                }
            }
            __syncthreads();

            // --- (c) trailing rank-32 update: 4x4 tiles, float4 both sides ---
            const int ntr = rem >> 2;
            const int ntiles = ntr * (ntr + 1) / 2;     // <= 300
            if (tid < ntiles) {
                int ti, tj;
                tridec(tid, ti, tj);
                const int ib = k0 + 32 + ti * 4;
                const int jb = k0 + 32 + tj * 4;
                int roi[4], roj[4];
                #pragma unroll
                for (int r = 0; r < 4; ++r) {
                    roi[r] = aoff(ib + r) + k0;
                    roj[r] = aoff(jb + r) + k0;
                }
                float acc[16];
                #pragma unroll
                for (int k = 0; k < 16; ++k) acc[k] = 0.0f;

                #pragma unroll
                for (int c4 = 0; c4 < 8; ++c4) {
                    float4 li[4], lj[4];
                    #pragma unroll
                    for (int r = 0; r < 4; ++r) {
                        li[r] = *reinterpret_cast<const float4*>(&Apk[roi[r] + c4 * 4]);
                        lj[r] = *reinterpret_cast<const float4*>(&Apk[roj[r] + c4 * 4]);
                    }
                    #pragma unroll
                    for (int r = 0; r < 4; ++r)
                        #pragma unroll
                        for (int s = 0; s < 4; ++s) {
                            acc[r * 4 + s] = fmaf(li[r].x, lj[s].x, acc[r * 4 + s]);
                            acc[r * 4 + s] = fmaf(li[r].y, lj[s].y, acc[r * 4 + s]);
                            acc[r * 4 + s] = fmaf(li[r].z, lj[s].z, acc[r * 4 + s]);
                            acc[r * 4 + s] = fmaf(li[r].w, lj[s].w, acc[r * 4 + s]);
                        }
                }
                #pragma unroll
                for (int r = 0; r < 4; ++r) {
                    const int i = ib + r;
                    const int ro = aoff(i);
                    #pragma unroll
                    for (int s = 0; s < 4; ++s) {
                        const int j = jb + s;
                        if (j <= i) Apk[ro + j] -= acc[r * 4 + s];
                    }
                }
            }
        }
    }
    __syncthreads();

    // ---- write chol (lower, zeros above) ----
    {
        const int i0 = (tid >> 4) * 4;
        const int j0 = (tid & 15) * 4;
        #pragma unroll
        for (int r = 0; r < 4; ++r) {
            const int i = i0 + r;
            const int ro = aoff(i);
            float va[8];
            #pragma unroll
            for (int c = 0; c < 8; ++c) {
                int j = (c < 4) ? (j0 + c) : (64 + j0 + (c - 4));
                va[c] = (j <= i) ? Apk[ro + j] : 0.0f;
            }
            *reinterpret_cast<float4*>(c_out + i * 128 + j0) =
                make_float4(va[0], va[1], va[2], va[3]);
            *reinterpret_cast<float4*>(c_out + i * 128 + 64 + j0) =
                make_float4(va[4], va[5], va[6], va[7]);
        }
    }
}

extern "C" void kernel_launch(void* const* d_in, const int* in_sizes, int n_in,
                              void* d_out, int out_size)
{
    const float* aug      = (const float*)d_in[0];
    const float* theta    = (const float*)d_in[1];
    const float* scales   = (const float*)d_in[2];
    const float* nug_mean = (const float*)d_in[3];
    const int*   bidx     = (const int*)d_in[4];
    float* out = (float*)d_out;

    const size_t smem_bytes = (size_t)SMEM_FLOATS * sizeof(float);
    cudaFuncSetAttribute(otm_fused_kernel,
                         cudaFuncAttributeMaxDynamicSharedMemorySize,
                         (int)smem_bytes);

    otm_fused_kernel<<<N_LOC, 512, smem_bytes>>>(aug, theta, scales, nug_mean,
                                                 bidx, out);
}

// round 5
// speedup vs baseline: 1.3362x; 1.3362x over previous
#include <cuda_runtime.h>
#include <math.h>

#define N_LOC 4096
#define N_REP 128
#define M_NBR 48

#define APK_FLOATS 8448          // packed lower triangle, rows padded to 4
#define XS_STRIDE 128

// smem layout (floats)
#define OFF_APK  0
#define OFF_XS   (APK_FLOATS)
#define OFF_DIAG (OFF_XS + M_NBR * XS_STRIDE)
#define OFF_INVD (OFF_DIAG + 128)
#define OFF_INVL (OFF_INVD + 16)
#define OFF_SCAL (OFF_INVL + 16 * 17)
#define SMEM_FLOATS (OFF_SCAL + 48)

// packed row offset: row i starts at 4*sum_{k=1..i} ceil(k/4)
__device__ __forceinline__ int aoff(int i) {
    int q = i >> 2;
    return 4 * (q + 1) * (2 * q + (i & 3));
}

__device__ __forceinline__ void tridec(int t, int& row, int& col) {
    int r = (int)((sqrtf(8.0f * (float)t + 1.0f) - 1.0f) * 0.5f);
    while ((r + 1) * (r + 2) / 2 <= t) ++r;
    while (r * (r + 1) / 2 > t) --r;
    row = r;
    col = t - r * (r + 1) / 2;
}

__global__ __launch_bounds__(512, 3)
void otm_fused_kernel(const float* __restrict__ aug,
                      const float* __restrict__ theta,
                      const float* __restrict__ scales,
                      const float* __restrict__ nug_mean,
                      const int* __restrict__ batch_idx,
                      float* __restrict__ out)
{
    const int N = blockIdx.x;
    const int tid = threadIdx.x;

    float* g_out = out + (size_t)N * 16384;
    float* c_out = out + (size_t)N_LOC * 16384 + (size_t)N * 16384;

    if (batch_idx[N] == 0) {
        for (int idx = tid; idx < 16384; idx += 512) {
            float v = ((idx >> 7) == (idx & 127)) ? 1.0f : 0.0f;
            g_out[idx] = v;
            c_out[idx] = v;
        }
        return;
    }

    extern __shared__ float smem[];
    float* Apk   = smem + OFF_APK;    // packed lower triangle
    float* xs    = smem + OFF_XS;     // [48][128] k-major
    float* diag  = smem + OFF_DIAG;   // [128]
    float* invd  = smem + OFF_INVD;   // [16]
    float* invL  = smem + OFF_INVL;   // [16][17]
    float* scalm = smem + OFF_SCAL;   // [48]

    const float t2 = theta[2];
    const float t3 = theta[3];
    const float t4 = theta[4];
    const float t5 = theta[5];
    const float ls = expf(t5) * 1.7320508075688772f;
    const float inv_ls2 = 1.0f / (ls * ls);
    const float sig2 = expf(2.0f * (logf(scales[N]) * t4 + t3));
    const float inv_nug = 1.0f / nug_mean[N];

    if (tid < M_NBR) {
        scalm[tid] = expf(-0.5f * (float)(tid + 1) * expf(t2));
    }
    __syncthreads();

    // ---- load xs[m][i] = clean(aug[i,N,1+m]) * scalm[m] ----
    {
        const float* base = aug + (size_t)N * (M_NBR + 1) + 1;
        for (int idx = tid; idx < N_REP * M_NBR; idx += 512) {
            int i = idx / M_NBR;
            int m = idx - i * M_NBR;
            float v = base[(size_t)i * ((size_t)N_LOC * (M_NBR + 1)) + m];
            if (v != v) v = 0.0f;
            xs[m * XS_STRIDE + i] = v * scalm[m];
        }
    }
    __syncthreads();

    // ---- diag[i] = sum_m xs[m][i]^2 ----
    if (tid < N_REP) {
        float d = 0.0f;
        #pragma unroll
        for (int m = 0; m < M_NBR; ++m) {
            float v = xs[m * XS_STRIDE + tid];
            d = fmaf(v, v, d);
        }
        diag[tid] = d;
    }
    __syncthreads();

    // ---- Gram + epilogue, LOWER TRIANGLE only: 528 4x4 tiles ----
    for (int t = tid; t < 528; t += 512) {
        int ti, tj;
        tridec(t, ti, tj);
        const int ib = ti * 4, jb = tj * 4;

        float acc[16];
        #pragma unroll
        for (int k = 0; k < 16; ++k) acc[k] = 0.0f;

        #pragma unroll 4
        for (int m = 0; m < M_NBR; ++m) {
            const float* row = xs + m * XS_STRIDE;
            float4 a = *reinterpret_cast<const float4*>(row + ib);
            float4 b = *reinterpret_cast<const float4*>(row + jb);
            float av[4] = {a.x, a.y, a.z, a.w};
            float bv[4] = {b.x, b.y, b.z, b.w};
            #pragma unroll
            for (int r = 0; r < 4; ++r)
                #pragma unroll
                for (int c = 0; c < 4; ++c)
                    acc[r * 4 + c] = fmaf(av[r], bv[c], acc[r * 4 + c]);
        }

        float di[4], dj[4];
        #pragma unroll
        for (int r = 0; r < 4; ++r) di[r] = diag[ib + r];
        #pragma unroll
        for (int c = 0; c < 4; ++c) dj[c] = diag[jb + c];

        #pragma unroll
        for (int r = 0; r < 4; ++r) {
            const int i = ib + r;
            const int ro = aoff(i);
            #pragma unroll
            for (int c = 0; c < 4; ++c) {
                const int j = jb + c;
                if (j <= i) {
                    float G = acc[r * 4 + c];
                    float sq = fmaxf((di[r] + dj[c] - 2.0f * G) * inv_ls2, 0.0f);
                    // s3 = sqrt(3*sq) via fast rsqrt (exact 0 handled by max clamp)
                    float s3 = 1.7320508075688772f * sq * __frsqrt_rn(fmaxf(sq, 1e-30f));
                    float mat = (1.0f + s3) * __expf(-s3);
                    float val = (G + sig2 * mat) * inv_nug + ((i == j) ? 1.0f : 0.0f);
                    Apk[ro + j] = val;
                }
            }
        }
    }
    __syncthreads();

    // ---- write g (full, mirrored from packed lower) ----
    {
        const int i0 = (tid >> 4) * 4;
        const int j0 = (tid & 15) * 4;
        int aj0[8];
        #pragma unroll
        for (int c = 0; c < 8; ++c) {
            int j = (c < 4) ? (j0 + c) : (64 + j0 + (c - 4));
            aj0[c] = aoff(j);
        }
        #pragma unroll
        for (int r = 0; r < 4; ++r) {
            const int i = i0 + r;
            const int ro = aoff(i);
            float va[8];
            #pragma unroll
            for (int c = 0; c < 8; ++c) {
                int j = (c < 4) ? (j0 + c) : (64 + j0 + (c - 4));
                va[c] = (j <= i) ? Apk[ro + j] : Apk[aj0[c] + i];
            }
            *reinterpret_cast<float4*>(g_out + i * 128 + j0) =
                make_float4(va[0], va[1], va[2], va[3]);
            *reinterpret_cast<float4*>(g_out + i * 128 + 64 + j0) =
                make_float4(va[4], va[5], va[6], va[7]);
        }
    }

    // ================= Blocked Cholesky (lower), NB=16, packed A ==========
    #pragma unroll 1
    for (int kb = 0; kb < 8; ++kb) {
        const int k0 = kb * 16;
        __syncthreads();

        // --- (a) warp0: factor 16x16 diag block in registers ---
        if (tid < 32) {
            const int lane = tid;
            float rw[16];
            const int ro = (lane < 16) ? aoff(k0 + lane) : 0;
            if (lane < 16) {
                #pragma unroll
                for (int j = 0; j < 16; ++j)
                    rw[j] = (j <= lane) ? Apk[ro + k0 + j] : 0.0f;
            } else {
                #pragma unroll
                for (int j = 0; j < 16; ++j) rw[j] = 0.0f;
            }
            #pragma unroll
            for (int c = 0; c < 16; ++c) {
                float dcc = __shfl_sync(0xffffffffu, rw[c], c);
                float lcc = sqrtf(dcc);
                float inv = 1.0f / lcc;
                if (lane == c) { rw[c] = lcc; invd[c] = inv; }
                else if (lane > c && lane < 16) rw[c] *= inv;
                float vc = rw[c];
                #pragma unroll
                for (int j = c + 1; j < 16; ++j) {
                    float vj = __shfl_sync(0xffffffffu, vc, j);
                    if (lane >= j && lane < 16) rw[j] -= vc * vj;
                }
            }
            if (lane < 16) {
                #pragma unroll
                for (int j = 0; j < 16; ++j)
                    if (j <= lane) Apk[ro + k0 + j] = rw[j];
            }
            __syncwarp();

            // --- (a2) lanes 0..15: column `lane` of inv(L11) into smem ---
            if (lane < 16) {
                float x[16];
                #pragma unroll
                for (int r = 0; r < 16; ++r) {
                    float s = (r == lane) ? 1.0f : 0.0f;
                    const int rr = aoff(k0 + r) + k0;
                    #pragma unroll
                    for (int d = 0; d < r; ++d)
                        s -= Apk[rr + d] * x[d];
                    x[r] = s * invd[r];
                    invL[r * 17 + lane] = x[r];
                }
            }
        }
        __syncthreads();

        const int rem = 112 - k0;
        if (rem > 0) {
            // --- (b) panel solve: row i = invL * row (parallel, depth 16) ---
            if (tid < rem) {
                const int i = k0 + 16 + tid;
                const int ro = aoff(i) + k0;
                float r[16];
                #pragma unroll
                for (int c4 = 0; c4 < 4; ++c4) {
                    float4 v = *reinterpret_cast<const float4*>(&Apk[ro + c4 * 4]);
                    r[c4 * 4 + 0] = v.x; r[c4 * 4 + 1] = v.y;
                    r[c4 * 4 + 2] = v.z; r[c4 * 4 + 3] = v.w;
                }
                #pragma unroll
                for (int c = 0; c < 16; ++c) {
                    float s = 0.0f;
                    #pragma unroll
                    for (int d = 0; d <= c; ++d)
                        s = fmaf(invL[c * 17 + d], r[d], s);
                    Apk[ro + c] = s;
                }
            }
            __syncthreads();

            // --- (c) trailing rank-16 update: 4x4 tiles, float2 loads ---
            const int ntr = rem >> 2;
            const int ntiles = ntr * (ntr + 1) / 2;     // <= 406
            if (tid < ntiles) {
                int ti, tj;
                tridec(tid, ti, tj);
                const int ib = k0 + 16 + ti * 4;
                const int jb = k0 + 16 + tj * 4;
                int roi[4], roj[4];
                #pragma unroll
                for (int r = 0; r < 4; ++r) {
                    roi[r] = aoff(ib + r) + k0;
                    roj[r] = aoff(jb + r) + k0;
                }
                float acc[16];
                #pragma unroll
                for (int k = 0; k < 16; ++k) acc[k] = 0.0f;

                #pragma unroll
                for (int c2 = 0; c2 < 8; ++c2) {
                    float2 li[4], lj[4];
                    #pragma unroll
                    for (int r = 0; r < 4; ++r) {
                        li[r] = *reinterpret_cast<const float2*>(&Apk[roi[r] + c2 * 2]);
                        lj[r] = *reinterpret_cast<const float2*>(&Apk[roj[r] + c2 * 2]);
                    }
                    #pragma unroll
                    for (int r = 0; r < 4; ++r)
                        #pragma unroll
                        for (int s = 0; s < 4; ++s) {
                            acc[r * 4 + s] = fmaf(li[r].x, lj[s].x, acc[r * 4 + s]);
                            acc[r * 4 + s] = fmaf(li[r].y, lj[s].y, acc[r * 4 + s]);
                        }
                }
                #pragma unroll
                for (int r = 0; r < 4; ++r) {
                    const int i = ib + r;
                    const int ro = aoff(i);
                    #pragma unroll
                    for (int s = 0; s < 4; ++s) {
                        const int j = jb + s;
                        if (j <= i) Apk[ro + j] -= acc[r * 4 + s];
                    }
                }
            }
        }
    }
    __syncthreads();

    // ---- write chol (lower, zeros above) ----
    {
        const int i0 = (tid >> 4) * 4;
        const int j0 = (tid & 15) * 4;
        #pragma unroll
        for (int r = 0; r < 4; ++r) {
            const int i = i0 + r;
            const int ro = aoff(i);
            float va[8];
            #pragma unroll
            for (int c = 0; c < 8; ++c) {
                int j = (c < 4) ? (j0 + c) : (64 + j0 + (c - 4));
                va[c] = (j <= i) ? Apk[ro + j] : 0.0f;
            }
            *reinterpret_cast<float4*>(c_out + i * 128 + j0) =
                make_float4(va[0], va[1], va[2], va[3]);
            *reinterpret_cast<float4*>(c_out + i * 128 + 64 + j0) =
                make_float4(va[4], va[5], va[6], va[7]);
        }
    }
}

extern "C" void kernel_launch(void* const* d_in, const int* in_sizes, int n_in,
                              void* d_out, int out_size)
{
    const float* aug      = (const float*)d_in[0];
    const float* theta    = (const float*)d_in[1];
    const float* scales   = (const float*)d_in[2];
    const float* nug_mean = (const float*)d_in[3];
    const int*   bidx     = (const int*)d_in[4];
    float* out = (float*)d_out;

    const size_t smem_bytes = (size_t)SMEM_FLOATS * sizeof(float);
    cudaFuncSetAttribute(otm_fused_kernel,
                         cudaFuncAttributeMaxDynamicSharedMemorySize,
                         (int)smem_bytes);

    otm_fused_kernel<<<N_LOC, 512, smem_bytes>>>(aug, theta, scales, nug_mean,
                                                 bidx, out);
}